// round 7
// baseline (speedup 1.0000x reference)
#include <cuda_runtime.h>
#include <cuda_bf16.h>
#include <cstdint>
#include <math.h>

// Problem constants
#define C_   8
#define NQ_  16
#define NK_  32
#define B_   128
#define D_   128
#define E_   512
#define H_   8
#define A_   64
#define OUT_ 64

// Scratch (allocation-free rule: device globals)
__device__ float g_query[C_ * NQ_ * B_ * E_];    // 33.5 MB
__device__ float g_key  [C_ * NK_ * B_ * E_];    // 67 MB
__device__ float g_value[C_ * NK_ * B_ * E_];    // 67 MB
__device__ float g_attno[C_ * NQ_ * B_ * E_];    // 33.5 MB

// ===========================================================================
// Helpers
// ===========================================================================
__device__ __forceinline__ uint32_t smem_to_u32(const void* p) {
    uint32_t a;
    asm("{ .reg .u64 t; cvta.to.shared.u64 t, %1; cvt.u32.u64 %0, t; }"
        : "=r"(a) : "l"(p));
    return a;
}

// ldmatrix: four / two 8x8 b16 matrices (baseline PTX, sm_75+)
#define LDSM_X4(r, addr) \
    asm volatile("ldmatrix.sync.aligned.m8n8.x4.shared.b16 {%0,%1,%2,%3}, [%4];" \
        : "=r"((r)[0]), "=r"((r)[1]), "=r"((r)[2]), "=r"((r)[3]) : "r"(addr))
#define LDSM_X2(r, addr) \
    asm volatile("ldmatrix.sync.aligned.m8n8.x2.shared.b16 {%0,%1}, [%2];" \
        : "=r"((r)[0]), "=r"((r)[1]) : "r"(addr))

// mma.sync m16n8k16 bf16 -> f32 (baseline PTX, sm_80+; compiles to HMMA)
#define MMA_BF16(d, a, b) \
    asm volatile("mma.sync.aligned.m16n8k16.row.col.f32.bf16.bf16.f32 " \
        "{%0,%1,%2,%3}, {%4,%5,%6,%7}, {%8,%9}, {%0,%1,%2,%3};" \
        : "+f"((d)[0]), "+f"((d)[1]), "+f"((d)[2]), "+f"((d)[3]) \
        : "r"((a)[0]), "r"((a)[1]), "r"((a)[2]), "r"((a)[3]), \
          "r"((b)[0]), "r"((b)[1]))

// Tile smem layout: [rows][128 bf16] = 256 B/row; 16 B chunk-swizzled so that
// ldmatrix's 8 consecutive rows at one chunk column hit 8 distinct bank groups.
__device__ __forceinline__ uint32_t toff(int row, int kk) {
    return ((uint32_t)row << 8)
         + ((uint32_t)(((kk >> 3) ^ (row & 7))) << 4)
         + ((uint32_t)(kk & 7) << 1);
}

// Split fp32 pair -> packed bf16x2 hi and lo words
__device__ __forceinline__ void split2(float a, float b, uint32_t& hi, uint32_t& lo) {
    __nv_bfloat16 h0 = __float2bfloat16(a);
    __nv_bfloat16 h1 = __float2bfloat16(b);
    float r0 = a - __bfloat162float(h0);
    float r1 = b - __bfloat162float(h1);
    __nv_bfloat16 l0 = __float2bfloat16(r0);
    __nv_bfloat16 l1 = __float2bfloat16(r1);
    hi = (uint32_t)__bfloat16_as_ushort(h0) | ((uint32_t)__bfloat16_as_ushort(h1) << 16);
    lo = (uint32_t)__bfloat16_as_ushort(l0) | ((uint32_t)__bfloat16_as_ushort(l1) << 16);
}

// Dynamic smem layout (bytes)
#define SM_PE     0          // 512 B
#define SM_AHI    1024       // 16 KB  (64 rows x 128 k bf16)
#define SM_ALO    17408      // 16 KB
#define SM_BHI    33792      // 32 KB  (128 n-rows x 128 k bf16 = W-slab transposed)
#define SM_BLO    66560      // 32 KB
#define SM_TOTAL  99328

// ---------------------------------------------------------------------------
// Kernel 1: split-bf16 HMMA fused QKV projection with positional encoding.
// grid = 1280: [0,256) Q, [256,768) K, [768,1280) V.
// One (c, n, proj, row-half) per block; 64-row M tiles -> 97 KB smem ->
// 2 CTAs/SM for cross-CTA staging/MMA overlap (fix for occ=12.5%/issue=11.6%).
// Block: Out[64B x 512E] = (X+PE)[64x128] @ W[128x512], 4 E-slabs of 128.
// D = Ahi*Bhi + Ahi*Blo + Alo*Bhi, fp32 register accumulate.
// 8 warps in 2(M) x 4(N) grid; each warp: 32x32 output = 2x4 m16n8 tiles.
// ---------------------------------------------------------------------------
__global__ __launch_bounds__(256, 2) void qkv_mma_kernel(
    const float* __restrict__ q, const float* __restrict__ k,
    const float* __restrict__ Wq, const float* __restrict__ Wk,
    const float* __restrict__ Wv)
{
    extern __shared__ char smem[];
    uint32_t sbase = smem_to_u32(smem);
    int t = threadIdx.x, wid = t >> 5, lane = t & 31;

    int bid = blockIdx.x;
    const float* X; const float* W; float* Out; int n, half;
    if (bid < 256) {
        int i = bid; int c = i >> 5; int r = i & 31; n = r >> 1; half = r & 1;
        X = q  + (size_t)(c * NQ_ + n) * B_ * D_;
        W = Wq + (size_t)(c * NQ_ + n) * D_ * E_;
        Out = g_query + (size_t)(c * NQ_ + n) * B_ * E_;
    } else if (bid < 768) {
        int i = bid - 256; int c = i >> 6; int r = i & 63; n = r >> 1; half = r & 1;
        X = k  + (size_t)(c * NK_ + n) * B_ * D_;
        W = Wk + (size_t)(c * NK_ + n) * D_ * E_;
        Out = g_key + (size_t)(c * NK_ + n) * B_ * E_;
    } else {
        int i = bid - 768; int c = i >> 6; int r = i & 63; n = r >> 1; half = r & 1;
        X = k  + (size_t)(c * NK_ + n) * B_ * D_;
        W = Wv + (size_t)(c * NK_ + n) * D_ * E_;
        Out = g_value + (size_t)(c * NK_ + n) * B_ * E_;
    }
    X   += (size_t)half * 64 * D_;     // this block's 64-row slice
    Out += (size_t)half * 64 * E_;

    float* pe = (float*)(smem + SM_PE);
    if (t < 128) {
        const float kc = -9.210340371976184f / 128.0f;  // -ln(10000)/D
        float w = expf((float)(t & ~1) * kc);
        pe[t] = (t & 1) ? cosf((float)n * w) : sinf((float)n * w);
    }
    __syncthreads();

    // ---- Stage A = X + PE (64 x 128), split into bf16 hi/lo ----
#pragma unroll
    for (int j = 0; j < 8; j++) {
        int it  = t + 256 * j;            // 2048 float4 items
        int row = it >> 5;                // 0..63
        int kk  = (it & 31) * 4;          // 0..124
        float4 v = *(const float4*)(X + (size_t)row * D_ + kk);
        v.x += pe[kk]; v.y += pe[kk + 1]; v.z += pe[kk + 2]; v.w += pe[kk + 3];
        uint32_t h0, l0, h1, l1;
        split2(v.x, v.y, h0, l0);
        split2(v.z, v.w, h1, l1);
        uint32_t off = toff(row, kk);
        *(uint2*)(smem + SM_AHI + off) = make_uint2(h0, h1);
        *(uint2*)(smem + SM_ALO + off) = make_uint2(l0, l1);
    }

    int m0 = (wid >> 2) * 32;     // warp M origin (0 or 32)
    int n0 = (wid & 3) * 32;      // warp N origin within slab

    for (int slab = 0; slab < 4; slab++) {
        const float* Wp = W + slab * 128;

        // ---- Stage B = W-slab transposed ([n][k], 128x128), hi/lo ----
#pragma unroll
        for (int j = 0; j < 8; j++) {
            int it  = t + 256 * j;        // 2048 items
            int nn0 = (it & 31) * 4;      // n block of 4
            int kp  = it >> 5;            // 0..63
            int kk  = kp * 2;
            float4 w0 = *(const float4*)(Wp + (size_t)kk * E_ + nn0);
            float4 w1 = *(const float4*)(Wp + (size_t)(kk + 1) * E_ + nn0);
            float a0[4] = {w0.x, w0.y, w0.z, w0.w};
            float a1[4] = {w1.x, w1.y, w1.z, w1.w};
#pragma unroll
            for (int e = 0; e < 4; e++) {
                int nn = nn0 + e;
                uint32_t h, l;
                split2(a0[e], a1[e], h, l);   // pair along k: (kk, kk+1)
                uint32_t off = toff(nn, kk);
                *(uint32_t*)(smem + SM_BHI + off) = h;
                *(uint32_t*)(smem + SM_BLO + off) = l;
            }
        }
        __syncthreads();

        // ---- MMA burst: 8 k-steps x 2x4 tiles x 3 split terms ----
        float acc[2][4][4];
#pragma unroll
        for (int mt = 0; mt < 2; mt++)
#pragma unroll
            for (int nt = 0; nt < 4; nt++)
#pragma unroll
                for (int r = 0; r < 4; r++) acc[mt][nt][r] = 0.f;

#pragma unroll
        for (int ks = 0; ks < 8; ks++) {
            uint32_t ah[2][4], al[2][4];
#pragma unroll
            for (int mt = 0; mt < 2; mt++) {
                int row = m0 + mt * 16 + (lane & 15);
                uint32_t ch = (uint32_t)(ks * 2 + (lane >> 4));
                uint32_t off = ((uint32_t)row << 8) + (((ch ^ (row & 7))) << 4);
                LDSM_X4(ah[mt], sbase + SM_AHI + off);
                LDSM_X4(al[mt], sbase + SM_ALO + off);
            }
            uint32_t bh[4][2], bl[4][2];
#pragma unroll
            for (int nt = 0; nt < 4; nt++) {
                int nr = n0 + nt * 8 + (lane & 7);
                uint32_t ch = (uint32_t)(ks * 2 + ((lane >> 3) & 1));
                uint32_t off = ((uint32_t)nr << 8) + (((ch ^ (nr & 7))) << 4);
                LDSM_X2(bh[nt], sbase + SM_BHI + off);
                LDSM_X2(bl[nt], sbase + SM_BLO + off);
            }
#pragma unroll
            for (int mt = 0; mt < 2; mt++)
#pragma unroll
                for (int nt = 0; nt < 4; nt++) {
                    MMA_BF16(acc[mt][nt], ah[mt], bh[nt]);
                    MMA_BF16(acc[mt][nt], ah[mt], bl[nt]);
                    MMA_BF16(acc[mt][nt], al[mt], bh[nt]);
                }
        }

        // ---- Epilogue: direct fp32 stores (float2 per fragment row) ----
#pragma unroll
        for (int mt = 0; mt < 2; mt++) {
            int row = m0 + mt * 16 + (lane >> 2);
#pragma unroll
            for (int nt = 0; nt < 4; nt++) {
                int col = slab * 128 + n0 + nt * 8 + (lane & 3) * 2;
                float2 v0 = make_float2(acc[mt][nt][0], acc[mt][nt][1]);
                float2 v1 = make_float2(acc[mt][nt][2], acc[mt][nt][3]);
                *(float2*)(Out + (size_t)row * E_ + col) = v0;
                *(float2*)(Out + (size_t)(row + 8) * E_ + col) = v1;
            }
        }
        if (slab < 3) __syncthreads();   // protect B tiles for next staging
    }
}

// ---------------------------------------------------------------------------
// Kernel 2: attention per (c, b, h). grid = 8192, 128 threads. (unchanged)
// ---------------------------------------------------------------------------
__global__ __launch_bounds__(128) void attn_kernel()
{
    int bid = blockIdx.x;
    int h = bid & 7;
    int b = (bid >> 3) & 127;
    int c = bid >> 10;
    int t = threadIdx.x;

    __shared__ float Qs[16 * 64];
    __shared__ float Ks[32 * 68];
    __shared__ float Vs[32 * 64];
    __shared__ float lg[16 * 33];
    __shared__ float rmax[16], rsum[16];

#pragma unroll
    for (int j = 0; j < 2; j++) {
        int i4 = t + 128 * j;
        int nq = i4 >> 4, a4 = i4 & 15;
        *(float4*)&Qs[nq * 64 + a4 * 4] =
            *(const float4*)(g_query + (size_t)((c * NQ_ + nq) * B_ + b) * E_ + h * A_ + a4 * 4);
    }
#pragma unroll
    for (int j = 0; j < 4; j++) {
        int i4 = t + 128 * j;
        int nk = i4 >> 4, a4 = i4 & 15;
        size_t goff = (size_t)((c * NK_ + nk) * B_ + b) * E_ + h * A_ + a4 * 4;
        *(float4*)&Ks[nk * 68 + a4 * 4] = *(const float4*)(g_key + goff);
        *(float4*)&Vs[nk * 64 + a4 * 4] = *(const float4*)(g_value + goff);
    }
    __syncthreads();

    int nk  = t & 31;
    int nq0 = t >> 5;
    {
        float s0 = 0.f, s1 = 0.f, s2 = 0.f, s3 = 0.f;
#pragma unroll
        for (int a4 = 0; a4 < 16; a4++) {
            float4 kv = *(const float4*)&Ks[nk * 68 + a4 * 4];
            float4 q0 = *(const float4*)&Qs[(nq0 + 0)  * 64 + a4 * 4];
            float4 q1 = *(const float4*)&Qs[(nq0 + 4)  * 64 + a4 * 4];
            float4 q2 = *(const float4*)&Qs[(nq0 + 8)  * 64 + a4 * 4];
            float4 q3 = *(const float4*)&Qs[(nq0 + 12) * 64 + a4 * 4];
            s0 += q0.x * kv.x + q0.y * kv.y + q0.z * kv.z + q0.w * kv.w;
            s1 += q1.x * kv.x + q1.y * kv.y + q1.z * kv.z + q1.w * kv.w;
            s2 += q2.x * kv.x + q2.y * kv.y + q2.z * kv.z + q2.w * kv.w;
            s3 += q3.x * kv.x + q3.y * kv.y + q3.z * kv.z + q3.w * kv.w;
        }
        const float inv_temp = 0.125f;
        lg[(nq0 + 0)  * 33 + nk] = s0 * inv_temp;
        lg[(nq0 + 4)  * 33 + nk] = s1 * inv_temp;
        lg[(nq0 + 8)  * 33 + nk] = s2 * inv_temp;
        lg[(nq0 + 12) * 33 + nk] = s3 * inv_temp;
    }
    __syncthreads();

    if (t < 16) {
        float m = -3.4028234e38f;
        for (int x = 0; x < 32; x++) m = fmaxf(m, lg[t * 33 + x]);
        rmax[t] = m;
    }
    __syncthreads();

#pragma unroll
    for (int j = 0; j < 4; j++) {
        int nq = nq0 + 4 * j;
        int id = nq * 33 + nk;
        lg[id] = expf(lg[id] - rmax[nq]);
    }
    __syncthreads();

    if (t < 16) {
        float s = 0.f;
        for (int x = 0; x < 32; x++) s += lg[t * 33 + x];
        rsum[t] = s;
    }
    __syncthreads();

    int a   = t & 63;
    int nqb = t >> 6;
    float racc[8];
#pragma unroll
    for (int j = 0; j < 8; j++) racc[j] = 0.f;
#pragma unroll
    for (int x = 0; x < 32; x++) {
        float v = Vs[x * 64 + a];
#pragma unroll
        for (int j = 0; j < 8; j++)
            racc[j] += lg[(nqb + 2 * j) * 33 + x] * v;
    }
#pragma unroll
    for (int j = 0; j < 8; j++) {
        int nq = nqb + 2 * j;
        g_attno[(size_t)((c * NQ_ + nq) * B_ + b) * E_ + h * A_ + a] = racc[j] / rsum[nq];
    }
}

// ---------------------------------------------------------------------------
// Kernel 3: output projection per (c, nq): [128 x 512] @ [512 x 64]. (unchanged)
// ---------------------------------------------------------------------------
__global__ __launch_bounds__(256) void proj_kernel(const float* __restrict__ Wp,
                                                   float* __restrict__ out)
{
    int bid   = blockIdx.x;
    int mtile = bid & 1;
    int gm    = bid >> 1;
    int nq    = gm & 15;
    int c     = gm >> 4;

    const float* Ap = g_attno + (size_t)((c * NQ_ + nq) * B_ + mtile * 64) * E_;
    const float* Bp = Wp + (size_t)(c * NQ_ + nq) * E_ * OUT_;
    float*       Op = out + (size_t)((c * NQ_ + nq) * B_ + mtile * 64) * OUT_;

    __shared__ float As[16 * 68];
    __shared__ float Bs[16 * 64];

    int t  = threadIdx.x;
    int tx = t & 15;
    int ty = t >> 4;

    float acc[4][4];
#pragma unroll
    for (int i = 0; i < 4; i++)
#pragma unroll
        for (int j = 0; j < 4; j++) acc[i][j] = 0.f;

    for (int kk = 0; kk < E_; kk += 16) {
        {
            int row = t >> 2;
            int c4  = (t & 3) * 4;
            float4 v = *(const float4*)(Ap + (size_t)row * E_ + kk + c4);
            As[(c4 + 0) * 68 + row] = v.x;
            As[(c4 + 1) * 68 + row] = v.y;
            As[(c4 + 2) * 68 + row] = v.z;
            As[(c4 + 3) * 68 + row] = v.w;
        }
        {
            int row = t >> 4;
            int cc  = (t & 15) * 4;
            *(float4*)&Bs[row * 64 + cc] = *(const float4*)(Bp + (size_t)(kk + row) * OUT_ + cc);
        }
        __syncthreads();

#pragma unroll
        for (int kq = 0; kq < 16; kq++) {
            float4 a4 = *(float4*)&As[kq * 68 + ty * 4];
            float4 b4 = *(float4*)&Bs[kq * 64 + tx * 4];
            float ra[4] = {a4.x, a4.y, a4.z, a4.w};
            float rb[4] = {b4.x, b4.y, b4.z, b4.w};
#pragma unroll
            for (int i = 0; i < 4; i++)
#pragma unroll
                for (int j = 0; j < 4; j++)
                    acc[i][j] += ra[i] * rb[j];
        }
        __syncthreads();
    }

#pragma unroll
    for (int i = 0; i < 4; i++) {
        float4 v;
        v.x = acc[i][0]; v.y = acc[i][1]; v.z = acc[i][2]; v.w = acc[i][3];
        *(float4*)(Op + (size_t)(ty * 4 + i) * OUT_ + tx * 4) = v;
    }
}

// ---------------------------------------------------------------------------
extern "C" void kernel_launch(void* const* d_in, const int* in_sizes, int n_in,
                              void* d_out, int out_size)
{
    (void)in_sizes; (void)n_in; (void)out_size;
    const float* q  = (const float*)d_in[0];
    const float* k  = (const float*)d_in[1];
    const float* Wq = (const float*)d_in[2];
    const float* Wk = (const float*)d_in[3];
    const float* Wv = (const float*)d_in[4];
    const float* Wp = (const float*)d_in[5];
    float* out = (float*)d_out;

    cudaFuncSetAttribute(qkv_mma_kernel,
                         cudaFuncAttributeMaxDynamicSharedMemorySize, SM_TOTAL);

    qkv_mma_kernel<<<1280, 256, SM_TOTAL>>>(q, k, Wq, Wk, Wv);
    attn_kernel<<<8192, 128>>>();
    proj_kernel<<<256, 256>>>(Wp, out);
}

// round 9
// speedup vs baseline: 1.4314x; 1.4314x over previous
#include <cuda_runtime.h>
#include <cuda_bf16.h>
#include <cstdint>
#include <math.h>

// Problem constants
#define C_   8
#define NQ_  16
#define NK_  32
#define B_   128
#define D_   128
#define E_   512
#define H_   8
#define A_   64
#define OUT_ 64

// Scratch (allocation-free rule: device globals)
__device__ float g_query[C_ * NQ_ * B_ * E_];    // 33.5 MB
__device__ float g_key  [C_ * NK_ * B_ * E_];    // 67 MB
__device__ float g_value[C_ * NK_ * B_ * E_];    // 67 MB
__device__ float g_attno[C_ * NQ_ * B_ * E_];    // 33.5 MB

// ===========================================================================
// Helpers
// ===========================================================================
__device__ __forceinline__ uint32_t smem_to_u32(const void* p) {
    uint32_t a;
    asm("{ .reg .u64 t; cvta.to.shared.u64 t, %1; cvt.u32.u64 %0, t; }"
        : "=r"(a) : "l"(p));
    return a;
}

// ldmatrix: 8x8 b16 matrices (baseline PTX, sm_75+)
#define LDSM_X4(r, addr) \
    asm volatile("ldmatrix.sync.aligned.m8n8.x4.shared.b16 {%0,%1,%2,%3}, [%4];" \
        : "=r"((r)[0]), "=r"((r)[1]), "=r"((r)[2]), "=r"((r)[3]) : "r"(addr))
#define LDSM_X4_T(r, addr) \
    asm volatile("ldmatrix.sync.aligned.m8n8.x4.trans.shared.b16 {%0,%1,%2,%3}, [%4];" \
        : "=r"((r)[0]), "=r"((r)[1]), "=r"((r)[2]), "=r"((r)[3]) : "r"(addr))

// mma.sync m16n8k16 bf16 -> f32 (baseline PTX, sm_80+)
#define MMA_BF16(d, a, b0, b1) \
    asm volatile("mma.sync.aligned.m16n8k16.row.col.f32.bf16.bf16.f32 " \
        "{%0,%1,%2,%3}, {%4,%5,%6,%7}, {%8,%9}, {%0,%1,%2,%3};" \
        : "+f"((d)[0]), "+f"((d)[1]), "+f"((d)[2]), "+f"((d)[3]) \
        : "r"((a)[0]), "r"((a)[1]), "r"((a)[2]), "r"((a)[3]), \
          "r"(b0), "r"(b1))

// Tile smem layout: [rows][128 bf16] = 256 B/row, 16B chunks swizzled by
// (chunk ^ (row & 7)) so ldmatrix's 8-row column access is conflict-free.
__device__ __forceinline__ uint32_t toff(int row, int kk) {
    return ((uint32_t)row << 8)
         + ((uint32_t)(((kk >> 3) ^ (row & 7))) << 4)
         + ((uint32_t)(kk & 7) << 1);
}

// Split fp32 pair -> packed bf16x2 hi and lo words
__device__ __forceinline__ void split2(float a, float b, uint32_t& hi, uint32_t& lo) {
    __nv_bfloat16 h0 = __float2bfloat16(a);
    __nv_bfloat16 h1 = __float2bfloat16(b);
    float r0 = a - __bfloat162float(h0);
    float r1 = b - __bfloat162float(h1);
    __nv_bfloat16 l0 = __float2bfloat16(r0);
    __nv_bfloat16 l1 = __float2bfloat16(r1);
    hi = (uint32_t)__bfloat16_as_ushort(h0) | ((uint32_t)__bfloat16_as_ushort(h1) << 16);
    lo = (uint32_t)__bfloat16_as_ushort(l0) | ((uint32_t)__bfloat16_as_ushort(l1) << 16);
}

// Dynamic smem layout (bytes)
#define SM_PE     0          // 512 B
#define SM_AHI    1024       // 32 KB  A: [m 128][k 128] bf16
#define SM_ALO    33792      // 32 KB
#define SM_BHI    66560      // 32 KB  B: [k 128][n 128] bf16 (natural, no transpose)
#define SM_BLO    99328      // 32 KB
#define SM_TOTAL  132096

// ---------------------------------------------------------------------------
// Kernel 1: split-bf16 HMMA fused QKV projection with positional encoding.
// grid = 640: [0,128) Q, [128,384) K, [384,640) V. One (c,n,proj) per block.
// 512 threads (16 warps -> 4 warps/SMSP for latency hiding), 1 CTA/SM.
// Block: Out[128B x 512E] = (X+PE)[128x128] @ W[128x512], 4 E-slabs of 128.
// B staged in natural [k][n] layout (conflict-free STS.128), fragments via
// ldmatrix.x4.trans. D = Ahi*Bhi + Ahi*Blo + Alo*Bhi, fp32 reg accumulate.
// Warp grid 2(M) x 8(N); warp tile 64x16 = 4x2 m16n8 tiles.
// ---------------------------------------------------------------------------
__global__ __launch_bounds__(512, 1) void qkv_mma_kernel(
    const float* __restrict__ q, const float* __restrict__ k,
    const float* __restrict__ Wq, const float* __restrict__ Wk,
    const float* __restrict__ Wv)
{
    extern __shared__ char smem[];
    uint32_t sbase = smem_to_u32(smem);
    int t = threadIdx.x, wid = t >> 5, lane = t & 31;

    int bid = blockIdx.x;
    const float* X; const float* W; float* Out; int n;
    if (bid < 128) {
        int i = bid; int c = i >> 4; n = i & 15;
        X = q  + (size_t)(c * NQ_ + n) * B_ * D_;
        W = Wq + (size_t)(c * NQ_ + n) * D_ * E_;
        Out = g_query + (size_t)(c * NQ_ + n) * B_ * E_;
    } else if (bid < 384) {
        int i = bid - 128; int c = i >> 5; n = i & 31;
        X = k  + (size_t)(c * NK_ + n) * B_ * D_;
        W = Wk + (size_t)(c * NK_ + n) * D_ * E_;
        Out = g_key + (size_t)(c * NK_ + n) * B_ * E_;
    } else {
        int i = bid - 384; int c = i >> 5; n = i & 31;
        X = k  + (size_t)(c * NK_ + n) * B_ * D_;
        W = Wv + (size_t)(c * NK_ + n) * D_ * E_;
        Out = g_value + (size_t)(c * NK_ + n) * B_ * E_;
    }

    float* pe = (float*)(smem + SM_PE);
    if (t < 128) {
        const float kc = -9.210340371976184f / 128.0f;  // -ln(10000)/D
        float w = expf((float)(t & ~1) * kc);
        pe[t] = (t & 1) ? cosf((float)n * w) : sinf((float)n * w);
    }
    __syncthreads();

    // ---- Stage A = X + PE (128 x 128), split hi/lo, [m][k] layout ----
#pragma unroll
    for (int j = 0; j < 8; j++) {
        int it  = t + 512 * j;            // 4096 float4 items
        int row = it >> 5;                // m: 0..127
        int kk  = (it & 31) * 4;          // k: 0..124
        float4 v = *(const float4*)(X + (size_t)row * D_ + kk);
        v.x += pe[kk]; v.y += pe[kk + 1]; v.z += pe[kk + 2]; v.w += pe[kk + 3];
        uint32_t h0, l0, h1, l1;
        split2(v.x, v.y, h0, l0);
        split2(v.z, v.w, h1, l1);
        uint32_t off = toff(row, kk);     // (kk&7)*2 in {0,8} -> uint2 aligned
        *(uint2*)(smem + SM_AHI + off) = make_uint2(h0, h1);
        *(uint2*)(smem + SM_ALO + off) = make_uint2(l0, l1);
    }

    int m0 = (wid >> 3) * 64;     // warp M origin (0 or 64)
    int n0 = (wid & 7) * 16;      // warp N origin within slab

    // Per-lane ldmatrix source addresses (row/chunk parts independent of ks):
    // A: matrices {m rows 0-7, 8-15} x {chunk c, c+1}
    // B (trans): matrices {k rows 0-7, 8-15} x {n-chunk nc0, nc0+1}
    int a_row_lo = lane & 15;          // + m0 + mt*16
    int a_chsel  = lane >> 4;          // 0 or 1
    int b_mat    = lane >> 3;
    int b_krow_lo = (b_mat & 1) * 8 + (lane & 7);   // + ks*16
    int b_nch    = (n0 >> 3) + (b_mat >> 1);

    for (int slab = 0; slab < 4; slab++) {
        const float* Wp = W + slab * 128;

        // ---- Stage B = W-slab (128k x 128n), natural [k][n], hi/lo ----
        // Item = (krow, 8-wide n-chunk): coalesced LDG, conflict-free STS.128.
#pragma unroll
        for (int j = 0; j < 4; j++) {
            int it   = t + 512 * j;       // 2048 items
            int nch  = it & 15;           // n-chunk: 0..15
            int krow = it >> 4;           // k: 0..127
            const float* src = Wp + (size_t)krow * E_ + nch * 8;
            float4 w0 = *(const float4*)(src);
            float4 w1 = *(const float4*)(src + 4);
            uint32_t h0, l0, h1, l1, h2, l2, h3, l3;
            split2(w0.x, w0.y, h0, l0);
            split2(w0.z, w0.w, h1, l1);
            split2(w1.x, w1.y, h2, l2);
            split2(w1.z, w1.w, h3, l3);
            uint32_t off = ((uint32_t)krow << 8)
                         + ((uint32_t)((nch ^ (krow & 7))) << 4);
            *(uint4*)(smem + SM_BHI + off) = make_uint4(h0, h1, h2, h3);
            *(uint4*)(smem + SM_BLO + off) = make_uint4(l0, l1, l2, l3);
        }
        __syncthreads();

        // ---- MMA burst: 8 k-steps x 4x2 tiles x 3 split terms ----
        float acc[4][2][4];
#pragma unroll
        for (int mt = 0; mt < 4; mt++)
#pragma unroll
            for (int nt = 0; nt < 2; nt++)
#pragma unroll
                for (int r = 0; r < 4; r++) acc[mt][nt][r] = 0.f;

#pragma unroll
        for (int ks = 0; ks < 8; ks++) {
            // B fragments: one X4-trans each for hi and lo
            uint32_t bh[4], bl[4];
            {
                int krow = ks * 16 + b_krow_lo;
                uint32_t off = ((uint32_t)krow << 8)
                             + ((uint32_t)((b_nch ^ (krow & 7))) << 4);
                LDSM_X4_T(bh, sbase + SM_BHI + off);
                LDSM_X4_T(bl, sbase + SM_BLO + off);
            }
            // A fragments + MMAs
#pragma unroll
            for (int mt = 0; mt < 4; mt++) {
                int row = m0 + mt * 16 + a_row_lo;
                uint32_t ch = (uint32_t)(ks * 2 + a_chsel);
                uint32_t off = ((uint32_t)row << 8) + (((ch ^ (row & 7))) << 4);
                uint32_t ah[4], al[4];
                LDSM_X4(ah, sbase + SM_AHI + off);
                LDSM_X4(al, sbase + SM_ALO + off);
                MMA_BF16(acc[mt][0], ah, bh[0], bh[1]);
                MMA_BF16(acc[mt][0], ah, bl[0], bl[1]);
                MMA_BF16(acc[mt][0], al, bh[0], bh[1]);
                MMA_BF16(acc[mt][1], ah, bh[2], bh[3]);
                MMA_BF16(acc[mt][1], ah, bl[2], bl[3]);
                MMA_BF16(acc[mt][1], al, bh[2], bh[3]);
            }
        }

        // ---- Epilogue: direct fp32 stores (float2 per fragment row) ----
#pragma unroll
        for (int mt = 0; mt < 4; mt++) {
            int row = m0 + mt * 16 + (lane >> 2);
#pragma unroll
            for (int nt = 0; nt < 2; nt++) {
                int col = slab * 128 + n0 + nt * 8 + (lane & 3) * 2;
                float2 v0 = make_float2(acc[mt][nt][0], acc[mt][nt][1]);
                float2 v1 = make_float2(acc[mt][nt][2], acc[mt][nt][3]);
                *(float2*)(Out + (size_t)row * E_ + col) = v0;
                *(float2*)(Out + (size_t)(row + 8) * E_ + col) = v1;
            }
        }
        if (slab < 3) __syncthreads();   // B tiles consumed before restaging
    }
}

// ---------------------------------------------------------------------------
// Kernel 2: attention per (c, b, h). grid = 8192, 128 threads. (unchanged)
// ---------------------------------------------------------------------------
__global__ __launch_bounds__(128) void attn_kernel()
{
    int bid = blockIdx.x;
    int h = bid & 7;
    int b = (bid >> 3) & 127;
    int c = bid >> 10;
    int t = threadIdx.x;

    __shared__ float Qs[16 * 64];
    __shared__ float Ks[32 * 68];
    __shared__ float Vs[32 * 64];
    __shared__ float lg[16 * 33];
    __shared__ float rmax[16], rsum[16];

#pragma unroll
    for (int j = 0; j < 2; j++) {
        int i4 = t + 128 * j;
        int nq = i4 >> 4, a4 = i4 & 15;
        *(float4*)&Qs[nq * 64 + a4 * 4] =
            *(const float4*)(g_query + (size_t)((c * NQ_ + nq) * B_ + b) * E_ + h * A_ + a4 * 4);
    }
#pragma unroll
    for (int j = 0; j < 4; j++) {
        int i4 = t + 128 * j;
        int nk = i4 >> 4, a4 = i4 & 15;
        size_t goff = (size_t)((c * NK_ + nk) * B_ + b) * E_ + h * A_ + a4 * 4;
        *(float4*)&Ks[nk * 68 + a4 * 4] = *(const float4*)(g_key + goff);
        *(float4*)&Vs[nk * 64 + a4 * 4] = *(const float4*)(g_value + goff);
    }
    __syncthreads();

    int nk  = t & 31;
    int nq0 = t >> 5;
    {
        float s0 = 0.f, s1 = 0.f, s2 = 0.f, s3 = 0.f;
#pragma unroll
        for (int a4 = 0; a4 < 16; a4++) {
            float4 kv = *(const float4*)&Ks[nk * 68 + a4 * 4];
            float4 q0 = *(const float4*)&Qs[(nq0 + 0)  * 64 + a4 * 4];
            float4 q1 = *(const float4*)&Qs[(nq0 + 4)  * 64 + a4 * 4];
            float4 q2 = *(const float4*)&Qs[(nq0 + 8)  * 64 + a4 * 4];
            float4 q3 = *(const float4*)&Qs[(nq0 + 12) * 64 + a4 * 4];
            s0 += q0.x * kv.x + q0.y * kv.y + q0.z * kv.z + q0.w * kv.w;
            s1 += q1.x * kv.x + q1.y * kv.y + q1.z * kv.z + q1.w * kv.w;
            s2 += q2.x * kv.x + q2.y * kv.y + q2.z * kv.z + q2.w * kv.w;
            s3 += q3.x * kv.x + q3.y * kv.y + q3.z * kv.z + q3.w * kv.w;
        }
        const float inv_temp = 0.125f;
        lg[(nq0 + 0)  * 33 + nk] = s0 * inv_temp;
        lg[(nq0 + 4)  * 33 + nk] = s1 * inv_temp;
        lg[(nq0 + 8)  * 33 + nk] = s2 * inv_temp;
        lg[(nq0 + 12) * 33 + nk] = s3 * inv_temp;
    }
    __syncthreads();

    if (t < 16) {
        float m = -3.4028234e38f;
        for (int x = 0; x < 32; x++) m = fmaxf(m, lg[t * 33 + x]);
        rmax[t] = m;
    }
    __syncthreads();

#pragma unroll
    for (int j = 0; j < 4; j++) {
        int nq = nq0 + 4 * j;
        int id = nq * 33 + nk;
        lg[id] = expf(lg[id] - rmax[nq]);
    }
    __syncthreads();

    if (t < 16) {
        float s = 0.f;
        for (int x = 0; x < 32; x++) s += lg[t * 33 + x];
        rsum[t] = s;
    }
    __syncthreads();

    int a   = t & 63;
    int nqb = t >> 6;
    float racc[8];
#pragma unroll
    for (int j = 0; j < 8; j++) racc[j] = 0.f;
#pragma unroll
    for (int x = 0; x < 32; x++) {
        float v = Vs[x * 64 + a];
#pragma unroll
        for (int j = 0; j < 8; j++)
            racc[j] += lg[(nqb + 2 * j) * 33 + x] * v;
    }
#pragma unroll
    for (int j = 0; j < 8; j++) {
        int nq = nqb + 2 * j;
        g_attno[(size_t)((c * NQ_ + nq) * B_ + b) * E_ + h * A_ + a] = racc[j] / rsum[nq];
    }
}

// ---------------------------------------------------------------------------
// Kernel 3: output projection per (c, nq): [128 x 512] @ [512 x 64]. (unchanged)
// ---------------------------------------------------------------------------
__global__ __launch_bounds__(256) void proj_kernel(const float* __restrict__ Wp,
                                                   float* __restrict__ out)
{
    int bid   = blockIdx.x;
    int mtile = bid & 1;
    int gm    = bid >> 1;
    int nq    = gm & 15;
    int c     = gm >> 4;

    const float* Ap = g_attno + (size_t)((c * NQ_ + nq) * B_ + mtile * 64) * E_;
    const float* Bp = Wp + (size_t)(c * NQ_ + nq) * E_ * OUT_;
    float*       Op = out + (size_t)((c * NQ_ + nq) * B_ + mtile * 64) * OUT_;

    __shared__ float As[16 * 68];
    __shared__ float Bs[16 * 64];

    int t  = threadIdx.x;
    int tx = t & 15;
    int ty = t >> 4;

    float acc[4][4];
#pragma unroll
    for (int i = 0; i < 4; i++)
#pragma unroll
        for (int j = 0; j < 4; j++) acc[i][j] = 0.f;

    for (int kk = 0; kk < E_; kk += 16) {
        {
            int row = t >> 2;
            int c4  = (t & 3) * 4;
            float4 v = *(const float4*)(Ap + (size_t)row * E_ + kk + c4);
            As[(c4 + 0) * 68 + row] = v.x;
            As[(c4 + 1) * 68 + row] = v.y;
            As[(c4 + 2) * 68 + row] = v.z;
            As[(c4 + 3) * 68 + row] = v.w;
        }
        {
            int row = t >> 4;
            int cc  = (t & 15) * 4;
            *(float4*)&Bs[row * 64 + cc] = *(const float4*)(Bp + (size_t)(kk + row) * OUT_ + cc);
        }
        __syncthreads();

#pragma unroll
        for (int kq = 0; kq < 16; kq++) {
            float4 a4 = *(float4*)&As[kq * 68 + ty * 4];
            float4 b4 = *(float4*)&Bs[kq * 64 + tx * 4];
            float ra[4] = {a4.x, a4.y, a4.z, a4.w};
            float rb[4] = {b4.x, b4.y, b4.z, b4.w};
#pragma unroll
            for (int i = 0; i < 4; i++)
#pragma unroll
                for (int j = 0; j < 4; j++)
                    acc[i][j] += ra[i] * rb[j];
        }
        __syncthreads();
    }

#pragma unroll
    for (int i = 0; i < 4; i++) {
        float4 v;
        v.x = acc[i][0]; v.y = acc[i][1]; v.z = acc[i][2]; v.w = acc[i][3];
        *(float4*)(Op + (size_t)(ty * 4 + i) * OUT_ + tx * 4) = v;
    }
}

// ---------------------------------------------------------------------------
extern "C" void kernel_launch(void* const* d_in, const int* in_sizes, int n_in,
                              void* d_out, int out_size)
{
    (void)in_sizes; (void)n_in; (void)out_size;
    const float* q  = (const float*)d_in[0];
    const float* k  = (const float*)d_in[1];
    const float* Wq = (const float*)d_in[2];
    const float* Wk = (const float*)d_in[3];
    const float* Wv = (const float*)d_in[4];
    const float* Wp = (const float*)d_in[5];
    float* out = (float*)d_out;

    cudaFuncSetAttribute(qkv_mma_kernel,
                         cudaFuncAttributeMaxDynamicSharedMemorySize, SM_TOTAL);

    qkv_mma_kernel<<<640, 512, SM_TOTAL>>>(q, k, Wq, Wk, Wv);
    attn_kernel<<<8192, 128>>>();
    proj_kernel<<<256, 256>>>(Wp, out);
}